// round 16
// baseline (speedup 1.0000x reference)
#include <cuda_runtime.h>

// QualityAwarePatchAugment — GB300 sm_103a — R12.
// Granularity trend (R8 MLP8/occ46 -> R11 MLP4/occ67, each a win) pushed to
// its endpoint: 1024 threads per patch, 2 float4 per thread, WARP = BATCH.
//   - warp w owns batch w's 256 px: lane loads f4 slots {lane, lane+32}
//   - full-warp butterfly reduce (no partial-width shuffles)
//   - launch_bounds(1024,2) caps regs at 32 (8 landing + ~20 bookkeeping)
//     -> 2 blocks/SM = 2048 threads = ~full occupancy; smem 33KB*2 fits.
// Structure otherwise identical to the proven R8/R11 skeleton: ONE
// unconditional barrier, redundant per-warp fold, smem only for blur.

__device__ __forceinline__ float clipf(float v) {
    return fminf(fmaxf(v, 0.0f), 1.0f);
}

__global__ void __launch_bounds__(1024, 2) fused_kernel(
    const float4* __restrict__ img,
    const float4* __restrict__ noise,
    float4*       __restrict__ out,
    const float*  __restrict__ r_strong,
    const float*  __restrict__ r_drop,
    const float*  __restrict__ r_else,
    const float*  __restrict__ bright_f,
    const float*  __restrict__ contrast_f,
    const float*  __restrict__ slight_f,
    const int*    __restrict__ aug_choice,
    const int*    __restrict__ slight_choice)
{
    __shared__ float sm[32 * 256];          // patch tile; used ONLY for blur
    __shared__ float sh_s[32], sh_s2[32];
    __shared__ float s_scal[8];

    const int p    = blockIdx.x;            // patch index = ph*64 + pw
    const int ph   = p >> 6;
    const int pw   = p & 63;
    const int t    = threadIdx.x;           // 0..1023
    const int b    = t >> 5;                // batch 0..31 == warp id
    const int lane = t & 31;

    // Prefetch decision scalars (before the barrier).
    if (t < 8) {
        float v;
        switch (t) {
            case 0: v = r_strong[p];                       break;
            case 1: v = r_drop[p];                         break;
            case 2: v = r_else[p];                         break;
            case 3: v = bright_f[p];                       break;
            case 4: v = contrast_f[p];                     break;
            case 5: v = slight_f[p];                       break;
            case 6: v = __int_as_float(aug_choice[p]);     break;
            default: v = __int_as_float(slight_choice[p]); break;
        }
        s_scal[t] = v;
    }

    // float4 base of (batch b, patch row 0); img row stride = 256 float4.
    const int f4base = (b << 18) + (ph << 12) + (pw << 2);

    // ---- Phase 1: load 2 float4s (slots lane, lane+32), warp reduce -------
    float4 v0, v1;
    {
        const int fi0 = lane;               // rows 0..7
        const int fi1 = lane + 32;          // rows 8..15
        v0 = img[f4base + ((fi0 >> 2) << 8) + (fi0 & 3)];
        v1 = img[f4base + ((fi1 >> 2) << 8) + (fi1 & 3)];
    }
    float s  = v0.x + v0.y + v0.z + v0.w + v1.x + v1.y + v1.z + v1.w;
    float s2 = v0.x * v0.x + v0.y * v0.y + v0.z * v0.z + v0.w * v0.w
             + v1.x * v1.x + v1.y * v1.y + v1.z * v1.z + v1.w * v1.w;
    #pragma unroll
    for (int off = 16; off; off >>= 1) {    // full-warp reduce (warp = batch)
        s  += __shfl_down_sync(0xffffffffu, s,  off);
        s2 += __shfl_down_sync(0xffffffffu, s2, off);
    }
    if (lane == 0) { sh_s[b] = s; sh_s2[b] = s2; }
    __syncthreads();                        // the only unconditional barrier

    // ---- Phase 2: redundant per-warp butterfly fold (all lanes get q,mpp) -
    float q, mpp;
    {
        const float bs  = sh_s[lane];
        const float bs2 = sh_s2[lane];
        const float mean = bs * (1.0f / 256.0f);
        float var = (bs2 - bs * bs * (1.0f / 256.0f)) * (1.0f / 255.0f); // ddof=1
        var = fmaxf(var, 0.0f);
        const float sd = sqrtf(var);
        const float iq = 1.0f - 2.0f * fabsf(mean - 0.5f);
        float qs  = (sd + iq + var) * (1.0f / 3.0f);
        float tot = bs;
        #pragma unroll
        for (int off = 16; off; off >>= 1) {
            qs  += __shfl_xor_sync(0xffffffffu, qs,  off);
            tot += __shfl_xor_sync(0xffffffffu, tot, off);
        }
        q   = qs  * (1.0f / 32.0f);
        mpp = tot * (1.0f / 8192.0f);       // 32 batches * 256 px
    }

    const bool low    = q < 0.7f;
    const bool strong = low && (s_scal[0] < 0.8f);
    const bool drop   = low && (q < 0.3f) && (s_scal[1] < 0.1f);
    const bool els    = (!low) && (s_scal[2] < 0.3f);

    int code = 0;
    if (strong) code = __float_as_int(s_scal[6]) + 1;   // aug_choice + 1
    if (els)    code = __float_as_int(s_scal[7]) + 5;   // slight_choice + 5
    if (drop)   code = 7;

    float param = 0.0f;
    switch (code) {
        case 1: param = 0.1f;       break;
        case 3: param = s_scal[3];  break;   // bright_f
        case 4: param = s_scal[4];  break;   // contrast_f
        case 5: param = 0.05f;      break;
        case 6: param = s_scal[5];  break;   // slight_f
        default: break;
    }

    // Global indices for this thread's two slots.
    const int fi0 = lane,      fi1 = lane + 32;
    const int gi0 = f4base + ((fi0 >> 2) << 8) + (fi0 & 3);
    const int gi1 = f4base + ((fi1 >> 2) << 8) + (fi1 & 3);

    // ---- Phase 3: apply (block-uniform branch; data lives in registers) ---
    if (code == 0) {                              // identity (~20%)
        out[gi0] = v0;
        out[gi1] = v1;
    } else if (code == 1 || code == 5) {          // noise / slight noise
        const float4 n0 = __ldcs(&noise[gi0]);
        const float4 n1 = __ldcs(&noise[gi1]);
        float4 o0, o1;
        o0.x = clipf(fmaf(param, n0.x, v0.x));
        o0.y = clipf(fmaf(param, n0.y, v0.y));
        o0.z = clipf(fmaf(param, n0.z, v0.z));
        o0.w = clipf(fmaf(param, n0.w, v0.w));
        o1.x = clipf(fmaf(param, n1.x, v1.x));
        o1.y = clipf(fmaf(param, n1.y, v1.y));
        o1.z = clipf(fmaf(param, n1.z, v1.z));
        o1.w = clipf(fmaf(param, n1.w, v1.w));
        out[gi0] = o0;
        out[gi1] = o1;
    } else if (code == 2) {                       // 3x3 blur: needs neighbors
        float* const sm_b = sm + (b << 8);        // [row16][col16] slice
        *reinterpret_cast<float4*>(
            sm_b + ((fi0 >> 2) << 4) + ((fi0 & 3) << 2)) = v0;
        *reinterpret_cast<float4*>(
            sm_b + ((fi1 >> 2) << 4) + ((fi1 & 3) << 2)) = v1;
        __syncthreads();                          // uniform: all threads here
        const float inv9 = 1.0f / 9.0f;
        #pragma unroll
        for (int k = 0; k < 2; k++) {
            const int fi  = k ? fi1 : fi0;
            const int row = fi >> 2;
            const int c0  = (fi & 3) << 2;
            float a0 = 0.f, a1 = 0.f, a2 = 0.f, a3 = 0.f;
            #pragma unroll
            for (int dr = -1; dr <= 1; dr++) {
                const int r = row + dr;
                if (r < 0 || r > 15) continue;    // zero padding in patch
                const float* rp = sm_b + (r << 4);
                const float lft = (c0 > 0)  ? rp[c0 - 1] : 0.0f;
                const float rgt = (c0 < 12) ? rp[c0 + 4] : 0.0f;
                const float m0 = rp[c0], m1 = rp[c0 + 1];
                const float m2 = rp[c0 + 2], m3 = rp[c0 + 3];
                a0 += lft + m0 + m1;
                a1 += m0 + m1 + m2;
                a2 += m1 + m2 + m3;
                a3 += m2 + m3 + rgt;
            }
            out[k ? gi1 : gi0] =
                make_float4(a0 * inv9, a1 * inv9, a2 * inv9, a3 * inv9);
        }
    } else if (code == 3 || code == 6) {          // brightness variants
        float4 o0, o1;
        o0.x = clipf(v0.x * param); o0.y = clipf(v0.y * param);
        o0.z = clipf(v0.z * param); o0.w = clipf(v0.w * param);
        o1.x = clipf(v1.x * param); o1.y = clipf(v1.y * param);
        o1.z = clipf(v1.z * param); o1.w = clipf(v1.w * param);
        out[gi0] = o0;
        out[gi1] = o1;
    } else if (code == 4) {                       // contrast about m_pp
        float4 o0, o1;
        o0.x = clipf(fmaf(v0.x - mpp, param, mpp));
        o0.y = clipf(fmaf(v0.y - mpp, param, mpp));
        o0.z = clipf(fmaf(v0.z - mpp, param, mpp));
        o0.w = clipf(fmaf(v0.w - mpp, param, mpp));
        o1.x = clipf(fmaf(v1.x - mpp, param, mpp));
        o1.y = clipf(fmaf(v1.y - mpp, param, mpp));
        o1.z = clipf(fmaf(v1.z - mpp, param, mpp));
        o1.w = clipf(fmaf(v1.w - mpp, param, mpp));
        out[gi0] = o0;
        out[gi1] = o1;
    } else {                                      // 7: drop -> zeros
        const float4 z = make_float4(0.f, 0.f, 0.f, 0.f);
        out[gi0] = z;
        out[gi1] = z;
    }
}

extern "C" void kernel_launch(void* const* d_in, const int* in_sizes, int n_in,
                              void* d_out, int out_size)
{
    fused_kernel<<<4096, 1024>>>(
        (const float4*)d_in[0],   // img
        (const float4*)d_in[1],   // noise
        (float4*)d_out,
        (const float*)d_in[2],    // r_strong
        (const float*)d_in[3],    // r_drop
        (const float*)d_in[4],    // r_else
        (const float*)d_in[5],    // bright_f
        (const float*)d_in[6],    // contrast_f
        (const float*)d_in[7],    // slight_f
        (const int*)d_in[8],      // aug_choice
        (const int*)d_in[9]);     // slight_choice
}